// round 7
// baseline (speedup 1.0000x reference)
#include <cuda_runtime.h>
#include <cuda_fp16.h>
#include <math.h>
#include <stdint.h>

#define Bdim 64
#define Tdim 1024
#define Idim 512
#define Hdim 512
#define N2H  1024

// ---- device scratch (static: no allocations allowed) ----
__device__ float g_z[Bdim * Tdim * Hdim];                       // z = sigmoid(xW+b), [B][T][H]
__device__ __align__(16) unsigned short g_yhi[2 * Bdim * Hdim]; // y hi fp16, [buf][b][h]
__device__ __align__(16) unsigned short g_ylo[2 * Bdim * Hdim]; // y lo fp16
__device__ unsigned g_cnt[8];                                    // per-group barrier counters

// ---------- acquire/release + async helpers ----------
__device__ __forceinline__ unsigned ld_acq(const unsigned* p) {
    unsigned v;
    asm volatile("ld.acquire.gpu.global.u32 %0, [%1];" : "=r"(v) : "l"(p) : "memory");
    return v;
}
__device__ __forceinline__ void red_rel_add(unsigned* p, unsigned v) {
    asm volatile("red.release.gpu.global.add.u32 [%0], %1;" :: "l"(p), "r"(v) : "memory");
}
__device__ __forceinline__ void spin_until(unsigned* cnt, unsigned target) {
    unsigned it = 0;
    while (ld_acq(cnt) < target) {
        if (++it > 2000000u) break;   // safety: fail fast (wrong answer), never hang
    }
}
__device__ __forceinline__ void cp16(uint32_t dst, const void* src) {
    asm volatile("cp.async.cg.shared.global [%0], [%1], 16;" :: "r"(dst), "l"(src) : "memory");
}
#define CP_COMMIT() asm volatile("cp.async.commit_group;" ::: "memory")
#define CP_WAIT0()  asm volatile("cp.async.wait_group 0;" ::: "memory")

__device__ __forceinline__ uint32_t smem_u32(const void* p) {
    uint32_t a;
    asm("{ .reg .u64 t; cvta.to.shared.u64 t, %1; cvt.u32.u64 %0, t; }" : "=r"(a) : "l"(p));
    return a;
}
__device__ __forceinline__ float tanh_fast(float x) {
    float e = __expf(2.f * x);
    return 1.f - 2.f / (e + 1.f);
}
__device__ __forceinline__ uint32_t packh2(__half a, __half b) {
    __half2 h = __halves2half2(a, b);
    return *(uint32_t*)&h;
}

#define LDSM_X4(r0, r1, r2, r3, addr) \
    asm volatile("ldmatrix.sync.aligned.m8n8.x4.shared.b16 {%0,%1,%2,%3}, [%4];" \
        : "=r"(r0), "=r"(r1), "=r"(r2), "=r"(r3) : "r"(addr))

#define MMA16816(d, a0, a1, a2, a3, b0, b1) \
    asm volatile("mma.sync.aligned.m16n8k16.row.col.f32.f16.f16.f32 " \
        "{%0,%1,%2,%3}, {%4,%5,%6,%7}, {%8,%9}, {%0,%1,%2,%3};" \
        : "+f"((d)[0]), "+f"((d)[1]), "+f"((d)[2]), "+f"((d)[3]) \
        : "r"(a0), "r"(a1), "r"(a2), "r"(a3), "r"(b0), "r"(b1))

// =====================================================================
// Phase 1: z = sigmoid(x @ W + bw).  FFMA SGEMM 128x128x16 (known-good).
// Also resets the phase-2 barrier counters.
// =====================================================================
#define BM 128
#define BN 128
#define BK 16
#define AST 132

__global__ __launch_bounds__(256) void phase1(const float* __restrict__ x,
                                              const float* __restrict__ W,
                                              const float* __restrict__ bw) {
    if (blockIdx.x == 0 && blockIdx.y == 0 && threadIdx.x < 8)
        g_cnt[threadIdx.x] = 0;

    __shared__ float As[BK * AST];
    __shared__ float Bs[BK * BN];

    const int tid = threadIdx.x;
    const int bn0 = blockIdx.x * BN;
    const int bm0 = blockIdx.y * BM;
    const int tm  = (tid >> 4) << 3;
    const int tn  = (tid & 15) << 3;

    float acc[8][8];
#pragma unroll
    for (int i = 0; i < 8; ++i)
#pragma unroll
        for (int j = 0; j < 8; ++j) acc[i][j] = 0.f;

    const int arow = tid >> 2;
    const int acol = (tid & 3) << 2;
    const int brow = tid >> 5;
    const int bcol = (tid & 31) << 2;

    for (int k0 = 0; k0 < Idim; k0 += BK) {
        float4 a0 = *(const float4*)&x[(size_t)(bm0 + arow)      * Idim + k0 + acol];
        float4 a1 = *(const float4*)&x[(size_t)(bm0 + arow + 64) * Idim + k0 + acol];
        float4 b0 = *(const float4*)&W[(size_t)(k0 + brow)     * Hdim + bn0 + bcol];
        float4 b1 = *(const float4*)&W[(size_t)(k0 + brow + 8) * Hdim + bn0 + bcol];
        __syncthreads();
        As[(acol + 0) * AST + arow] = a0.x;
        As[(acol + 1) * AST + arow] = a0.y;
        As[(acol + 2) * AST + arow] = a0.z;
        As[(acol + 3) * AST + arow] = a0.w;
        As[(acol + 0) * AST + arow + 64] = a1.x;
        As[(acol + 1) * AST + arow + 64] = a1.y;
        As[(acol + 2) * AST + arow + 64] = a1.z;
        As[(acol + 3) * AST + arow + 64] = a1.w;
        *(float4*)&Bs[brow * BN + bcol]       = b0;
        *(float4*)&Bs[(brow + 8) * BN + bcol] = b1;
        __syncthreads();
#pragma unroll
        for (int k = 0; k < BK; ++k) {
            float4 ra0 = *(const float4*)&As[k * AST + tm];
            float4 ra1 = *(const float4*)&As[k * AST + tm + 4];
            float4 rb0 = *(const float4*)&Bs[k * BN + tn];
            float4 rb1 = *(const float4*)&Bs[k * BN + tn + 4];
            float av[8] = {ra0.x, ra0.y, ra0.z, ra0.w, ra1.x, ra1.y, ra1.z, ra1.w};
            float bv[8] = {rb0.x, rb0.y, rb0.z, rb0.w, rb1.x, rb1.y, rb1.z, rb1.w};
#pragma unroll
            for (int i = 0; i < 8; ++i)
#pragma unroll
                for (int j = 0; j < 8; ++j) acc[i][j] += av[i] * bv[j];
        }
    }

    float bias[8];
#pragma unroll
    for (int j = 0; j < 8; ++j) bias[j] = bw[bn0 + tn + j];
#pragma unroll
    for (int i = 0; i < 8; ++i) {
        const size_t mg = (size_t)(bm0 + tm + i);
        float v[8];
#pragma unroll
        for (int j = 0; j < 8; ++j) {
            float p = acc[i][j] + bias[j];
            v[j] = 1.f / (1.f + __expf(-p));
        }
        *(float4*)&g_z[mg * Hdim + bn0 + tn]     = make_float4(v[0], v[1], v[2], v[3]);
        *(float4*)&g_z[mg * Hdim + bn0 + tn + 4] = make_float4(v[4], v[5], v[6], v[7]);
    }
}

// =====================================================================
// Phase 2: ping-pong HMMA recurrence.
// 128 CTAs = 2 sets x 64.  Set s hosts groups P=2s (batches 32s..+15)
// and Q=2s+1 (batches 32s+16..+31).  CTA c owns h-cols [8c,8c+8):
// N=16 mma cols = 8 i-cols + 8 o-cols; R fragments shared by P and Q.
// 8 warps = 2 n-tiles x 4 K-quarters (K=128/warp), 3-term fp16 split.
// Per iteration: P compute (Q's barrier drains + y loads in shadow),
// then Q compute (P's in shadow).  cp.async y-exchange, split
// arrive/wait barriers, double-buffered global y.
// =====================================================================
// dynamic smem layout (bytes):
//   sP_hi 0, sP_lo 16384, sQ_hi 32768, sQ_lo 49152, red4 65536..69632
#define SM2_RED 65536
#define SM2_SIZE 69632

__device__ __forceinline__ void mma_phase3(uint32_t aH, uint32_t aL, int kq, int cq, int lr,
                                           const uint32_t (&bhf)[8][2],
                                           const uint32_t (&blf)[8][2],
                                           float4* slot) {
    float dhh[4] = {0, 0, 0, 0}, dlh[4] = {0, 0, 0, 0}, dhl[4] = {0, 0, 0, 0};
#pragma unroll
    for (int kt = 0; kt < 8; ++kt) {
        const int ktg = kq * 8 + kt;
        const uint32_t xoff = (uint32_t)(((ktg * 2 + cq) ^ lr) << 4);
        uint32_t ah0, ah1, ah2, ah3, al0, al1, al2, al3;
        LDSM_X4(ah0, ah1, ah2, ah3, aH + xoff);
        LDSM_X4(al0, al1, al2, al3, aL + xoff);
        MMA16816(dhh, ah0, ah1, ah2, ah3, bhf[kt][0], bhf[kt][1]);
        MMA16816(dlh, al0, al1, al2, al3, bhf[kt][0], bhf[kt][1]);
        MMA16816(dhl, ah0, ah1, ah2, ah3, blf[kt][0], blf[kt][1]);
    }
    *slot = make_float4(dhh[0] + dlh[0] + dhl[0], dhh[1] + dlh[1] + dhl[1],
                        dhh[2] + dlh[2] + dhl[2], dhh[3] + dlh[3] + dhl[3]);
}

__device__ __forceinline__ void do_epilogue(
    const float4* red4, int lane, int t, int tail,
    int bgA, int bgB, int h0,
    float bi0, float bi1, float bo0, float bo1,
    float& cA0, float& cA1, float& cB0, float& cB1,
    float2 zA, float2 zB, float* __restrict__ out)
{
    float4 iS = make_float4(0, 0, 0, 0), oS = make_float4(0, 0, 0, 0);
#pragma unroll
    for (int j2 = 0; j2 < 4; ++j2) {
        const float4 a = red4[(2 * j2) * 32 + lane];
        const float4 b = red4[(2 * j2 + 1) * 32 + lane];
        iS.x += a.x; iS.y += a.y; iS.z += a.z; iS.w += a.w;
        oS.x += b.x; oS.y += b.y; oS.z += b.z; oS.w += b.w;
    }
    const float ivA0 = tanh_fast(iS.x + bi0), ivA1 = tanh_fast(iS.y + bi1);
    const float ivB0 = tanh_fast(iS.z + bi0), ivB1 = tanh_fast(iS.w + bi1);
    const float ovA0 = tanh_fast(oS.x + bo0), ovA1 = tanh_fast(oS.y + bo1);
    const float ovB0 = tanh_fast(oS.z + bo0), ovB1 = tanh_fast(oS.w + bo1);

    cA0 += ivA0 * zA.x;  cA1 += ivA1 * zA.y;
    cB0 += ivB0 * zB.x;  cB1 += ivB1 * zB.y;

    const float yA0 = ovA0 * tanh_fast(cA0);
    const float yA1 = ovA1 * tanh_fast(cA1);
    const float yB0 = ovB0 * tanh_fast(cB0);
    const float yB1 = ovB1 * tanh_fast(cB1);

    *(float2*)&out[((size_t)t * Bdim + bgA) * Hdim + h0] = make_float2(yA0, yA1);
    *(float2*)&out[((size_t)t * Bdim + bgB) * Hdim + h0] = make_float2(yB0, yB1);

    const int nbuf = (t + 1) & 1;
    const __half hA0 = __float2half_rn(yA0), hA1 = __float2half_rn(yA1);
    const __half hB0 = __float2half_rn(yB0), hB1 = __float2half_rn(yB1);
    *(uint32_t*)&g_yhi[((size_t)nbuf * Bdim + bgA) * Hdim + h0] = packh2(hA0, hA1);
    *(uint32_t*)&g_yhi[((size_t)nbuf * Bdim + bgB) * Hdim + h0] = packh2(hB0, hB1);
    *(uint32_t*)&g_ylo[((size_t)nbuf * Bdim + bgA) * Hdim + h0] =
        packh2(__float2half_rn(yA0 - __half2float(hA0)),
               __float2half_rn(yA1 - __half2float(hA1)));
    *(uint32_t*)&g_ylo[((size_t)nbuf * Bdim + bgB) * Hdim + h0] =
        packh2(__float2half_rn(yB0 - __half2float(hB0)),
               __float2half_rn(yB1 - __half2float(hB1)));

    if (tail && t == Tdim - 1) {
        const size_t base = (size_t)Tdim * Bdim * Hdim;
        out[base + (size_t)bgA * Hdim + h0]     = yA0;
        out[base + (size_t)bgA * Hdim + h0 + 1] = yA1;
        out[base + (size_t)bgB * Hdim + h0]     = yB0;
        out[base + (size_t)bgB * Hdim + h0 + 1] = yB1;
        const size_t cb = base + (size_t)Bdim * Hdim;
        out[cb + (size_t)bgA * Hdim + h0]     = cA0;
        out[cb + (size_t)bgA * Hdim + h0 + 1] = cA1;
        out[cb + (size_t)bgB * Hdim + h0]     = cB0;
        out[cb + (size_t)bgB * Hdim + h0 + 1] = cB1;
    }
}

__global__ __launch_bounds__(256, 1) void phase2(const float* __restrict__ Rm,
                                                 const float* __restrict__ br,
                                                 const float* __restrict__ y0,
                                                 const float* __restrict__ c0,
                                                 float* __restrict__ out,
                                                 int tail) {
    extern __shared__ __align__(16) unsigned char smem[];
    float4* red4 = (float4*)(smem + SM2_RED);

    const int tid  = threadIdx.x;
    const int w    = tid >> 5;
    const int lane = tid & 31;
    const int set  = blockIdx.x >> 6;      // 0..1
    const int c    = blockIdx.x & 63;      // 0..63
    const int nt   = w & 1;
    const int kq   = w >> 1;               // 0..3
    const int tig  = lane & 3;
    const int gid  = lane >> 2;
    const int q    = lane >> 3;
    const int lr   = lane & 7;
    const int cq   = q >> 1;
    const int rowA = lr + (q & 1) * 8;

    unsigned* cntP = &g_cnt[2 * set];
    unsigned* cntQ = &g_cnt[2 * set + 1];
    const int bbP = 32 * set;
    const int bbQ = 32 * set + 16;

    // ---- resident B fragments (shared by P and Q): R cols hi/lo fp16 ----
    uint32_t bh[8][2], bl[8][2];
    {
        const int nCol = (nt ? 512 : 0) + 8 * c + gid;
#pragma unroll
        for (int kt = 0; kt < 8; ++kt) {
            const int k0 = kq * 128 + kt * 16 + tig * 2;
            float v0 = Rm[(size_t)(k0)     * N2H + nCol];
            float v1 = Rm[(size_t)(k0 + 1) * N2H + nCol];
            float v2 = Rm[(size_t)(k0 + 8) * N2H + nCol];
            float v3 = Rm[(size_t)(k0 + 9) * N2H + nCol];
            __half h0h = __float2half_rn(v0), h1h = __float2half_rn(v1);
            __half h2h = __float2half_rn(v2), h3h = __float2half_rn(v3);
            bh[kt][0] = packh2(h0h, h1h);
            bh[kt][1] = packh2(h2h, h3h);
            bl[kt][0] = packh2(__float2half_rn(v0 - __half2float(h0h)),
                               __float2half_rn(v1 - __half2float(h1h)));
            bl[kt][1] = packh2(__float2half_rn(v2 - __half2float(h2h)),
                               __float2half_rn(v3 - __half2float(h3h)));
        }
    }

    // ---- smem A bases (swizzled rows of 1024B) ----
    const uint32_t sb  = smem_u32(smem);
    const uint32_t aPH = sb + (uint32_t)rowA * 1024u;
    const uint32_t aPL = aPH + 16384u;
    const uint32_t aQH = aPH + 32768u;
    const uint32_t aQL = aPH + 49152u;

    // ---- epilogue state: w0 -> group P, w1 -> group Q ----
    const int h0 = 8 * c + tig * 2;
    const int bb = (w == 1) ? bbQ : bbP;
    const int bgA = bb + gid, bgB = bb + gid + 8;
    float bi0 = 0, bi1 = 0, bo0 = 0, bo1 = 0;
    float cA0 = 0, cA1 = 0, cB0 = 0, cB1 = 0;
    if (w < 2) {
        bi0 = br[h0];       bi1 = br[h0 + 1];
        bo0 = br[512 + h0]; bo1 = br[512 + h0 + 1];
        cA0 = c0[(size_t)bgA * Hdim + h0];
        cA1 = c0[(size_t)bgA * Hdim + h0 + 1];
        cB0 = c0[(size_t)bgB * Hdim + h0];
        cB1 = c0[(size_t)bgB * Hdim + h0 + 1];
    }

    // ---- prologue: fill smemP/smemQ with split(y0) (local, no barrier) ----
    for (int i = tid; i < 2 * 16 * 512; i += 256) {
        const int ph  = i >> 13;                 // 0:P 1:Q
        const int idx = i & 8191;
        const int row = idx >> 9, col = idx & 511;
        const float v = y0[(size_t)((ph ? bbQ : bbP) + row) * Hdim + col];
        const __half hi = __float2half_rn(v);
        const __half lo = __float2half_rn(v - __half2float(hi));
        const int soff = row * 1024 + ((((col >> 3)) ^ (row & 7)) << 4) + (col & 7) * 2;
        *(__half*)(smem + ph * 32768 + soff)         = hi;
        *(__half*)(smem + ph * 32768 + 16384 + soff) = lo;
    }
    __syncthreads();

    for (int t = 0; t < Tdim; ++t) {
        // ---- z prefetch for both groups (DRAM, long slack) ----
        float2 zA, zB;
        if (w < 2) {
            zA = __ldcs((const float2*)&g_z[((size_t)bgA * Tdim + t) * Hdim + h0]);
            zB = __ldcs((const float2*)&g_z[((size_t)bgB * Tdim + t) * Hdim + h0]);
        }

        // ================= P phase =================
        mma_phase3(aPH, aPL, kq, cq, lr, bh, bl, &red4[w * 32 + lane]);
        if (tid == 0 && t > 0) spin_until(cntQ, 64u * (unsigned)t);
        __syncthreads();    // red4 ready + yQ(t) globally complete

        if (t > 0) {        // load yQ(t) -> smemQ (hidden behind epilogue P)
            const int buf = t & 1;
            const unsigned short* srcH = g_yhi + ((size_t)buf * Bdim + bbQ) * Hdim;
            const unsigned short* srcL = g_ylo + ((size_t)buf * Bdim + bbQ) * Hdim;
#pragma unroll
            for (int i2 = 0; i2 < 4; ++i2) {
                const int u = tid + i2 * 256;
                const int row = u >> 6, ch = u & 63;
                const uint32_t dst = sb + 32768u + (uint32_t)(row * 1024 + ((ch ^ (row & 7)) << 4));
                cp16(dst,          srcH + row * 512 + ch * 8);
                cp16(dst + 16384u, srcL + row * 512 + ch * 8);
            }
            CP_COMMIT();
        }
        if (w == 0)
            do_epilogue(red4, lane, t, tail, bgA, bgB, h0,
                        bi0, bi1, bo0, bo1, cA0, cA1, cB0, cB1, zA, zB, out);
        __syncthreads();    // epilogue stores ordered before release; red4 free
        if (tid == 0) red_rel_add(cntP, 1u);
        CP_WAIT0();
        __syncthreads();    // smemQ ready

        // ================= Q phase =================
        mma_phase3(aQH, aQL, kq, cq, lr, bh, bl, &red4[w * 32 + lane]);
        if (tid == 0 && t < Tdim - 1) spin_until(cntP, 64u * (unsigned)(t + 1));
        __syncthreads();

        if (t < Tdim - 1) { // load yP(t+1) -> smemP (hidden behind epilogue Q)
            const int buf = (t + 1) & 1;
            const unsigned short* srcH = g_yhi + ((size_t)buf * Bdim + bbP) * Hdim;
            const unsigned short* srcL = g_ylo + ((size_t)buf * Bdim + bbP) * Hdim;
#pragma unroll
            for (int i2 = 0; i2 < 4; ++i2) {
                const int u = tid + i2 * 256;
                const int row = u >> 6, ch = u & 63;
                const uint32_t dst = sb + (uint32_t)(row * 1024 + ((ch ^ (row & 7)) << 4));
                cp16(dst,          srcH + row * 512 + ch * 8);
                cp16(dst + 16384u, srcL + row * 512 + ch * 8);
            }
            CP_COMMIT();
        }
        if (w == 1)
            do_epilogue(red4, lane, t, tail, bgA, bgB, h0,
                        bi0, bi1, bo0, bo1, cA0, cA1, cB0, cB1, zA, zB, out);
        __syncthreads();
        if (tid == 0) red_rel_add(cntQ, 1u);
        CP_WAIT0();
        __syncthreads();    // smemP ready
    }
}

// =====================================================================
extern "C" void kernel_launch(void* const* d_in, const int* in_sizes, int n_in,
                              void* d_out, int out_size) {
    const float* x  = (const float*)d_in[0];
    const float* W  = (const float*)d_in[1];
    const float* R  = (const float*)d_in[2];
    const float* br = (const float*)d_in[3];
    const float* bw = (const float*)d_in[4];
    const float* y0 = (const float*)d_in[5];
    const float* c0 = (const float*)d_in[6];
    float* out = (float*)d_out;

    cudaFuncSetAttribute(phase2, cudaFuncAttributeMaxDynamicSharedMemorySize, SM2_SIZE);

    dim3 g1(Hdim / BN, (Bdim * Tdim) / BM);   // (4, 512)
    phase1<<<g1, 256>>>(x, W, bw);

    const long long full = (long long)Tdim * Bdim * Hdim + 2LL * Bdim * Hdim;
    const int tail = ((long long)out_size >= full) ? 1 : 0;
    phase2<<<128, 256, SM2_SIZE>>>(R, br, y0, c0, out, tail);
}

// round 8
// speedup vs baseline: 1.2231x; 1.2231x over previous
#include <cuda_runtime.h>
#include <cuda_fp16.h>
#include <math.h>
#include <stdint.h>

#define Bdim 64
#define Tdim 1024
#define Idim 512
#define Hdim 512
#define N2H  1024

// ---- device scratch (static: no allocations allowed) ----
__device__ float g_z[Bdim * Tdim * Hdim];                       // z = sigmoid(xW+b), [B][T][H]
__device__ __align__(16) unsigned short g_yhi[2 * Bdim * Hdim]; // y hi fp16, [buf][b][h]
__device__ __align__(16) unsigned short g_ylo[2 * Bdim * Hdim]; // y lo fp16
__device__ unsigned g_cnt[8];                                    // per-group barrier counters

// ---------- acquire/release helpers ----------
__device__ __forceinline__ unsigned ld_acq(const unsigned* p) {
    unsigned v;
    asm volatile("ld.acquire.gpu.global.u32 %0, [%1];" : "=r"(v) : "l"(p) : "memory");
    return v;
}
__device__ __forceinline__ void red_rel_add(unsigned* p, unsigned v) {
    asm volatile("red.release.gpu.global.add.u32 [%0], %1;" :: "l"(p), "r"(v) : "memory");
}
__device__ __forceinline__ void spin_until(unsigned* cnt, unsigned target) {
    unsigned it = 0;
    while (ld_acq(cnt) < target) {
        if (++it > 2000000u) break;   // safety: fail fast, never hang
    }
}
__device__ __forceinline__ void group_barrier(unsigned* cnt, unsigned target) {
    __syncthreads();
    if (threadIdx.x == 0) {
        red_rel_add(cnt, 1u);
        spin_until(cnt, target);
    }
    __syncthreads();
}

__device__ __forceinline__ uint32_t smem_u32(const void* p) {
    uint32_t a;
    asm("{ .reg .u64 t; cvta.to.shared.u64 t, %1; cvt.u32.u64 %0, t; }" : "=r"(a) : "l"(p));
    return a;
}
__device__ __forceinline__ float tanh_fast(float x) {
    float e = __expf(2.f * x);
    return 1.f - 2.f / (e + 1.f);
}
__device__ __forceinline__ uint32_t packh2(__half a, __half b) {
    __half2 h = __halves2half2(a, b);
    return *(uint32_t*)&h;
}

#define LDSM_X4(r0, r1, r2, r3, addr) \
    asm volatile("ldmatrix.sync.aligned.m8n8.x4.shared.b16 {%0,%1,%2,%3}, [%4];" \
        : "=r"(r0), "=r"(r1), "=r"(r2), "=r"(r3) : "r"(addr))

#define LDSM_X2(r0, r1, addr) \
    asm volatile("ldmatrix.sync.aligned.m8n8.x2.shared.b16 {%0,%1}, [%2];" \
        : "=r"(r0), "=r"(r1) : "r"(addr))

#define MMA16816(d, a0, a1, a2, a3, b0, b1) \
    asm volatile("mma.sync.aligned.m16n8k16.row.col.f32.f16.f16.f32 " \
        "{%0,%1,%2,%3}, {%4,%5,%6,%7}, {%8,%9}, {%0,%1,%2,%3};" \
        : "+f"((d)[0]), "+f"((d)[1]), "+f"((d)[2]), "+f"((d)[3]) \
        : "r"(a0), "r"(a1), "r"(a2), "r"(a3), "r"(b0), "r"(b1))

// =====================================================================
// Phase 1: z = sigmoid(x @ W + bw), HMMA 3-term fp16 split.
// CTA tile 128m x 128n, K chunks of 64.  8 warps = 2m x 4n, warp tile
// 64m x 32n.  A = x (m,k) hi/lo swizzled smem; B = W staged transposed
// as (n,k) hi/lo.  Also resets phase-2 barrier counters.
// =====================================================================
#define P1_SMEM 65536   // 4 x 16KB: Ahi, Alo, Bhi, Blo

__global__ __launch_bounds__(256) void phase1(const float* __restrict__ x,
                                              const float* __restrict__ W,
                                              const float* __restrict__ bw) {
    if (blockIdx.x == 0 && blockIdx.y == 0 && threadIdx.x < 8)
        g_cnt[threadIdx.x] = 0;

    extern __shared__ __align__(16) unsigned char sm1[];
    unsigned char* sAh = sm1;
    unsigned char* sAl = sm1 + 16384;
    unsigned char* sBh = sm1 + 32768;
    unsigned char* sBl = sm1 + 49152;
    const uint32_t uAh = smem_u32(sAh), uAl = smem_u32(sAl);
    const uint32_t uBh = smem_u32(sBh), uBl = smem_u32(sBl);

    const int tid = threadIdx.x;
    const int w = tid >> 5, lane = tid & 31;
    const int wm = w >> 2, wn = w & 3;
    const int m0 = blockIdx.y * 128;
    const int n0 = blockIdx.x * 128;

    const int q = lane >> 3, lr = lane & 7, cq = q >> 1;
    const int rowA = lr + (q & 1) * 8;
    const int rowB = lane & 7;
    const int cb = (lane >> 3) & 1;

    float acc[4][4][4];
#pragma unroll
    for (int a = 0; a < 4; ++a)
#pragma unroll
        for (int b = 0; b < 4; ++b)
#pragma unroll
            for (int cc = 0; cc < 4; ++cc) acc[a][b][cc] = 0.f;

    for (int kc = 0; kc < 8; ++kc) {
        const int k0 = kc * 64;
        __syncthreads();
        // ---- stage A: x[m0..+128][k0..+64] fp32 -> hi/lo fp16, swizzled ----
#pragma unroll
        for (int i = 0; i < 8; ++i) {
            const int s = tid + i * 256;            // 0..2047 float4 slots
            const int r = s >> 4;                    // 0..127
            const int c4 = (s & 15) << 2;            // 0..60
            const float4 v = *(const float4*)&x[(size_t)(m0 + r) * Idim + k0 + c4];
            const __half h0 = __float2half_rn(v.x), h1 = __float2half_rn(v.y);
            const __half h2 = __float2half_rn(v.z), h3 = __float2half_rn(v.w);
            const int base = r * 128 + ((((c4 >> 3)) ^ (r & 7)) << 4) + ((c4 >> 2) & 1) * 8;
            *(uint2*)(sAh + base) = make_uint2(packh2(h0, h1), packh2(h2, h3));
            *(uint2*)(sAl + base) = make_uint2(
                packh2(__float2half_rn(v.x - __half2float(h0)),
                       __float2half_rn(v.y - __half2float(h1))),
                packh2(__float2half_rn(v.z - __half2float(h2)),
                       __float2half_rn(v.w - __half2float(h3))));
        }
        // ---- stage B: W[k0..+64][n0..+128] -> transposed (n,k), hi/lo ----
#pragma unroll
        for (int i = 0; i < 32; ++i) {
            const int s2 = tid + i * 256;            // 0..8191
            const int kk = s2 >> 7, nn = s2 & 127;
            const float v = W[(size_t)(k0 + kk) * Hdim + n0 + nn];
            const __half hv = __float2half_rn(v);
            const int ad = nn * 128 + ((((kk >> 3)) ^ (nn & 7)) << 4) + (kk & 7) * 2;
            *(__half*)(sBh + ad) = hv;
            *(__half*)(sBl + ad) = __float2half_rn(v - __half2float(hv));
        }
        __syncthreads();
        // ---- mma over 4 k16 steps ----
#pragma unroll
        for (int kt = 0; kt < 4; ++kt) {
            uint32_t ah[4][4], al[4][4], bhf[4][2], blf[4][2];
#pragma unroll
            for (int mt = 0; mt < 4; ++mt) {
                const int r = wm * 64 + mt * 16 + rowA;
                const uint32_t off = (uint32_t)(r * 128 + (((2 * kt + cq) ^ (r & 7)) << 4));
                LDSM_X4(ah[mt][0], ah[mt][1], ah[mt][2], ah[mt][3], uAh + off);
                LDSM_X4(al[mt][0], al[mt][1], al[mt][2], al[mt][3], uAl + off);
            }
#pragma unroll
            for (int nt = 0; nt < 4; ++nt) {
                const int rn = wn * 32 + nt * 8 + rowB;
                const uint32_t offb = (uint32_t)(rn * 128 + (((2 * kt + cb) ^ (rn & 7)) << 4));
                LDSM_X2(bhf[nt][0], bhf[nt][1], uBh + offb);
                LDSM_X2(blf[nt][0], blf[nt][1], uBl + offb);
            }
#pragma unroll
            for (int mt = 0; mt < 4; ++mt)
#pragma unroll
                for (int nt = 0; nt < 4; ++nt) {
                    MMA16816(acc[mt][nt], ah[mt][0], ah[mt][1], ah[mt][2], ah[mt][3],
                             bhf[nt][0], bhf[nt][1]);
                    MMA16816(acc[mt][nt], al[mt][0], al[mt][1], al[mt][2], al[mt][3],
                             bhf[nt][0], bhf[nt][1]);
                    MMA16816(acc[mt][nt], ah[mt][0], ah[mt][1], ah[mt][2], ah[mt][3],
                             blf[nt][0], blf[nt][1]);
                }
        }
    }

    // ---- epilogue: bias + sigmoid + store ----
    const int gid = lane >> 2, tig = lane & 3;
#pragma unroll
    for (int nt = 0; nt < 4; ++nt) {
        const int gn = n0 + wn * 32 + nt * 8 + tig * 2;
        const float b0 = bw[gn], b1 = bw[gn + 1];
#pragma unroll
        for (int mt = 0; mt < 4; ++mt) {
            const int gm = m0 + wm * 64 + mt * 16 + gid;
            const float z0 = 1.f / (1.f + __expf(-(acc[mt][nt][0] + b0)));
            const float z1 = 1.f / (1.f + __expf(-(acc[mt][nt][1] + b1)));
            const float z2 = 1.f / (1.f + __expf(-(acc[mt][nt][2] + b0)));
            const float z3 = 1.f / (1.f + __expf(-(acc[mt][nt][3] + b1)));
            *(float2*)&g_z[(size_t)gm * Hdim + gn]       = make_float2(z0, z1);
            *(float2*)&g_z[(size_t)(gm + 8) * Hdim + gn] = make_float2(z2, z3);
        }
    }
}

// =====================================================================
// Phase 2: HMMA recurrence (R5 architecture, slimmer sync path).
// 128 CTAs = 4 groups x 32.  Group g owns batches [16g,16g+16).
// CTA c owns h [16c,16c+16): 4 n-tiles (2 i + 2 o); 8 warps =
// 4 n-tiles x 2 K-halves; B = R fragments resident in registers
// (hi/lo fp16, 3-term split).  Per step:
//   mma -> red4 -> syncthreads
//   w0,w1: epilogue -> bar.sync(1,64) -> tid0 release
//   all warps: per-lane acquire-spin -> load y(t+1) -> syncthreads
// =====================================================================
__global__ __launch_bounds__(256, 1) void phase2(const float* __restrict__ Rm,
                                                 const float* __restrict__ br,
                                                 const float* __restrict__ y0,
                                                 const float* __restrict__ c0,
                                                 float* __restrict__ out,
                                                 int tail) {
    __shared__ __align__(16) unsigned char sAhi[16 * 1024];   // 16 rows x 512 fp16
    __shared__ __align__(16) unsigned char sAlo[16 * 1024];
    __shared__ float4 red4[8 * 32];

    const int tid  = threadIdx.x;
    const int w    = tid >> 5;
    const int lane = tid & 31;
    const int g    = blockIdx.x >> 5;     // 0..3
    const int c    = blockIdx.x & 31;     // 0..31
    const int cbase = c * 16;
    const int nw = w & 3;                 // n-tile
    const int kh = w >> 2;                // K half
    const int tig = lane & 3;
    const int gid = lane >> 2;
    unsigned* cnt = &g_cnt[g];

    // ---- resident B fragments: R slice hi/lo fp16 ----
    uint32_t bh[16][2], bl[16][2];
    {
        const int nCol = (nw < 2) ? (cbase + nw * 8 + gid)
                                  : (512 + cbase + (nw - 2) * 8 + gid);
#pragma unroll
        for (int kt = 0; kt < 16; ++kt) {
            const int k0 = (kh * 16 + kt) * 16 + tig * 2;
            float v0 = Rm[(size_t)(k0)     * N2H + nCol];
            float v1 = Rm[(size_t)(k0 + 1) * N2H + nCol];
            float v2 = Rm[(size_t)(k0 + 8) * N2H + nCol];
            float v3 = Rm[(size_t)(k0 + 9) * N2H + nCol];
            __half h0 = __float2half_rn(v0), h1 = __float2half_rn(v1);
            __half h2 = __float2half_rn(v2), h3 = __float2half_rn(v3);
            bh[kt][0] = packh2(h0, h1);
            bh[kt][1] = packh2(h2, h3);
            bl[kt][0] = packh2(__float2half_rn(v0 - __half2float(h0)),
                               __float2half_rn(v1 - __half2float(h1)));
            bl[kt][1] = packh2(__float2half_rn(v2 - __half2float(h2)),
                               __float2half_rn(v3 - __half2float(h3)));
        }
    }

    // ---- ldmatrix lane addressing ----
    const int q  = lane >> 3;
    const int lr = lane & 7;
    const int rowA = lr + (q & 1) * 8;
    const int cq   = q >> 1;
    const uint32_t aHiBase = smem_u32(sAhi) + (uint32_t)rowA * 1024u;
    const uint32_t aLoBase = smem_u32(sAlo) + (uint32_t)rowA * 1024u;

    // ---- epilogue state (warps 0,1) ----
    const int h0  = cbase + nw * 8 + tig * 2;
    const int gbA = g * 16 + gid;
    const int gbB = gbA + 8;
    float bi0 = 0, bi1 = 0, bo0 = 0, bo1 = 0;
    float cA0 = 0, cA1 = 0, cB0 = 0, cB1 = 0;
    if (w < 2) {
        bi0 = br[h0];       bi1 = br[h0 + 1];
        bo0 = br[512 + h0]; bo1 = br[512 + h0 + 1];
        cA0 = c0[(size_t)gbA * Hdim + h0];
        cA1 = c0[(size_t)gbA * Hdim + h0 + 1];
        cB0 = c0[(size_t)gbB * Hdim + h0];
        cB1 = c0[(size_t)gbB * Hdim + h0 + 1];
    }

    // ---- init y buffer 0 (CTA 0 of each group) ----
    if (c == 0) {
        for (int i = tid; i < 16 * 512; i += 256) {
            const int row = i >> 9, col = i & 511;
            const float v = y0[(size_t)(g * 16 + row) * Hdim + col];
            const __half hi = __float2half_rn(v);
            g_yhi[(size_t)(g * 16 + row) * 512 + col] = *(const unsigned short*)&hi;
            const __half lo = __float2half_rn(v - __half2float(hi));
            g_ylo[(size_t)(g * 16 + row) * 512 + col] = *(const unsigned short*)&lo;
        }
    }
    group_barrier(cnt, 32u);    // cnt = 32 after all prologues

    // ---- load y(0) into smem ----
    {
        const uint4* srcH = (const uint4*)(g_yhi + (size_t)(g * 16) * 512);
        const uint4* srcL = (const uint4*)(g_ylo + (size_t)(g * 16) * 512);
#pragma unroll
        for (int i = 0; i < 4; ++i) {
            const int u = tid + i * 256;
            const int row = u >> 6, ch = u & 63;
            const uint4 vh = __ldcg(srcH + u);
            const uint4 vl = __ldcg(srcL + u);
            const int soff = row * 1024 + ((ch ^ (row & 7)) << 4);
            *(uint4*)(sAhi + soff) = vh;
            *(uint4*)(sAlo + soff) = vl;
        }
    }
    __syncthreads();

    // ---- prefetch z(0) ----
    float2 zA = make_float2(0, 0), zB = make_float2(0, 0);
    if (w < 2) {
        zA = __ldcs((const float2*)&g_z[((size_t)gbA * Tdim + 0) * Hdim + h0]);
        zB = __ldcs((const float2*)&g_z[((size_t)gbB * Tdim + 0) * Hdim + h0]);
    }

    for (int t = 0; t < Tdim; ++t) {
        // ---- 3-term split mma over this warp's K half ----
        {
            float dhh[4] = {0, 0, 0, 0}, dlh[4] = {0, 0, 0, 0}, dhl[4] = {0, 0, 0, 0};
#pragma unroll
            for (int kt = 0; kt < 16; ++kt) {
                const int ktg = kh * 16 + kt;
                const uint32_t xoff = (uint32_t)(((ktg * 2 + cq) ^ lr) << 4);
                uint32_t ah0, ah1, ah2, ah3, al0, al1, al2, al3;
                LDSM_X4(ah0, ah1, ah2, ah3, aHiBase + xoff);
                LDSM_X4(al0, al1, al2, al3, aLoBase + xoff);
                MMA16816(dhh, ah0, ah1, ah2, ah3, bh[kt][0], bh[kt][1]);
                MMA16816(dlh, al0, al1, al2, al3, bh[kt][0], bh[kt][1]);
                MMA16816(dhl, ah0, ah1, ah2, ah3, bl[kt][0], bl[kt][1]);
            }
            red4[w * 32 + lane] = make_float4(dhh[0] + dlh[0] + dhl[0],
                                              dhh[1] + dlh[1] + dhl[1],
                                              dhh[2] + dlh[2] + dhl[2],
                                              dhh[3] + dlh[3] + dhl[3]);
        }
        __syncthreads();    // red4 ready; y smem reads (ldsm) complete

        // ---- epilogue (warps 0,1), then release ----
        if (w < 2) {
            const float4 iA = red4[w * 32 + lane];
            const float4 iB = red4[(w + 4) * 32 + lane];
            const float4 oA = red4[(w + 2) * 32 + lane];
            const float4 oB = red4[(w + 6) * 32 + lane];

            const float ivA0 = tanh_fast(iA.x + iB.x + bi0);
            const float ivA1 = tanh_fast(iA.y + iB.y + bi1);
            const float ivB0 = tanh_fast(iA.z + iB.z + bi0);
            const float ivB1 = tanh_fast(iA.w + iB.w + bi1);
            const float ovA0 = tanh_fast(oA.x + oB.x + bo0);
            const float ovA1 = tanh_fast(oA.y + oB.y + bo1);
            const float ovB0 = tanh_fast(oA.z + oB.z + bo0);
            const float ovB1 = tanh_fast(oA.w + oB.w + bo1);

            cA0 += ivA0 * zA.x;  cA1 += ivA1 * zA.y;
            cB0 += ivB0 * zB.x;  cB1 += ivB1 * zB.y;

            const float yA0 = ovA0 * tanh_fast(cA0);
            const float yA1 = ovA1 * tanh_fast(cA1);
            const float yB0 = ovB0 * tanh_fast(cB0);
            const float yB1 = ovB1 * tanh_fast(cB1);

            *(float2*)&out[((size_t)t * Bdim + gbA) * Hdim + h0] = make_float2(yA0, yA1);
            *(float2*)&out[((size_t)t * Bdim + gbB) * Hdim + h0] = make_float2(yB0, yB1);

            const int nbuf = (t + 1) & 1;
            const __half hA0 = __float2half_rn(yA0), hA1 = __float2half_rn(yA1);
            const __half hB0 = __float2half_rn(yB0), hB1 = __float2half_rn(yB1);
            *(uint32_t*)&g_yhi[((size_t)nbuf * Bdim + gbA) * Hdim + h0] = packh2(hA0, hA1);
            *(uint32_t*)&g_yhi[((size_t)nbuf * Bdim + gbB) * Hdim + h0] = packh2(hB0, hB1);
            *(uint32_t*)&g_ylo[((size_t)nbuf * Bdim + gbA) * Hdim + h0] =
                packh2(__float2half_rn(yA0 - __half2float(hA0)),
                       __float2half_rn(yA1 - __half2float(hA1)));
            *(uint32_t*)&g_ylo[((size_t)nbuf * Bdim + gbB) * Hdim + h0] =
                packh2(__float2half_rn(yB0 - __half2float(hB0)),
                       __float2half_rn(yB1 - __half2float(hB1)));

            if (tail && t == Tdim - 1) {
                const size_t base = (size_t)Tdim * Bdim * Hdim;
                out[base + (size_t)gbA * Hdim + h0]     = yA0;
                out[base + (size_t)gbA * Hdim + h0 + 1] = yA1;
                out[base + (size_t)gbB * Hdim + h0]     = yB0;
                out[base + (size_t)gbB * Hdim + h0 + 1] = yB1;
                const size_t cb = base + (size_t)Bdim * Hdim;
                out[cb + (size_t)gbA * Hdim + h0]     = cA0;
                out[cb + (size_t)gbA * Hdim + h0 + 1] = cA1;
                out[cb + (size_t)gbB * Hdim + h0]     = cB0;
                out[cb + (size_t)gbB * Hdim + h0 + 1] = cB1;
            }

            // y stores of BOTH epilogue warps ordered before the release
            asm volatile("bar.sync 1, 64;" ::: "memory");
            if (tid == 0) red_rel_add(cnt, 1u);
        }

        // ---- all warps: acquire-spin, then load y(t+1) ----
        if (t < Tdim - 1) {
            spin_until(cnt, 32u * (unsigned)(t + 2));   // per-lane acquire
            const int buf = (t + 1) & 1;
            const uint4* srcH = (const uint4*)(g_yhi + ((size_t)buf * Bdim + g * 16) * 512);
            const uint4* srcL = (const uint4*)(g_ylo + ((size_t)buf * Bdim + g * 16) * 512);
#pragma unroll
            for (int i = 0; i < 4; ++i) {
                const int u = tid + i * 256;
                const int row = u >> 6, ch = u & 63;
                const uint4 vh = __ldcg(srcH + u);
                const uint4 vl = __ldcg(srcL + u);
                const int soff = row * 1024 + ((ch ^ (row & 7)) << 4);
                *(uint4*)(sAhi + soff) = vh;
                *(uint4*)(sAlo + soff) = vl;
            }
            if (w < 2) {    // prefetch z(t+1); consumed after next mma+sync
                zA = __ldcs((const float2*)&g_z[((size_t)gbA * Tdim + t + 1) * Hdim + h0]);
                zB = __ldcs((const float2*)&g_z[((size_t)gbB * Tdim + t + 1) * Hdim + h0]);
            }
            __syncthreads();    // y smem complete before next mma
        }
    }
}

// =====================================================================
extern "C" void kernel_launch(void* const* d_in, const int* in_sizes, int n_in,
                              void* d_out, int out_size) {
    const float* x  = (const float*)d_in[0];
    const float* W  = (const float*)d_in[1];
    const float* R  = (const float*)d_in[2];
    const float* br = (const float*)d_in[3];
    const float* bw = (const float*)d_in[4];
    const float* y0 = (const float*)d_in[5];
    const float* c0 = (const float*)d_in[6];
    float* out = (float*)d_out;

    cudaFuncSetAttribute(phase1, cudaFuncAttributeMaxDynamicSharedMemorySize, P1_SMEM);

    dim3 g1(Hdim / 128, (Bdim * Tdim) / 128);   // (4, 512)
    phase1<<<g1, 256, P1_SMEM>>>(x, W, bw);

    const long long full = (long long)Tdim * Bdim * Hdim + 2LL * Bdim * Hdim;
    const int tail = ((long long)out_size >= full) ? 1 : 0;
    phase2<<<128, 256>>>(R, br, y0, c0, out, tail);
}

// round 9
// speedup vs baseline: 1.2771x; 1.0441x over previous
#include <cuda_runtime.h>
#include <cuda_fp16.h>
#include <math.h>
#include <stdint.h>

#define Bdim 64
#define Tdim 1024
#define Idim 512
#define Hdim 512
#define N2H  1024

// ---- device scratch (static: no allocations allowed) ----
__device__ float g_z[Bdim * Tdim * Hdim];                       // z = sigmoid(xW+b), [B][T][H]
__device__ __align__(16) unsigned short g_yhi[2 * Bdim * Hdim]; // y hi fp16, [buf][b][h]
__device__ __align__(16) unsigned short g_ylo[2 * Bdim * Hdim]; // y lo fp16
__device__ unsigned g_cnt[8];                                    // per-group barrier counters

// ---------- acquire/release helpers ----------
__device__ __forceinline__ unsigned ld_acq(const unsigned* p) {
    unsigned v;
    asm volatile("ld.acquire.gpu.global.u32 %0, [%1];" : "=r"(v) : "l"(p) : "memory");
    return v;
}
__device__ __forceinline__ void red_rel_add(unsigned* p, unsigned v) {
    asm volatile("red.release.gpu.global.add.u32 [%0], %1;" :: "l"(p), "r"(v) : "memory");
}
__device__ __forceinline__ void spin_until(unsigned* cnt, unsigned target) {
    unsigned it = 0;
    while (ld_acq(cnt) < target) {
        if (++it > 2000000u) break;   // safety: fail fast, never hang
    }
}
__device__ __forceinline__ void group_barrier(unsigned* cnt, unsigned target) {
    __syncthreads();
    if (threadIdx.x == 0) {
        red_rel_add(cnt, 1u);
        spin_until(cnt, target);
    }
    __syncthreads();
}

__device__ __forceinline__ uint32_t smem_u32(const void* p) {
    uint32_t a;
    asm("{ .reg .u64 t; cvta.to.shared.u64 t, %1; cvt.u32.u64 %0, t; }" : "=r"(a) : "l"(p));
    return a;
}
__device__ __forceinline__ float tanh_fast(float x) {
    float e = __expf(2.f * x);
    return 1.f - 2.f / (e + 1.f);
}
__device__ __forceinline__ uint32_t packh2(__half a, __half b) {
    __half2 h = __halves2half2(a, b);
    return *(uint32_t*)&h;
}

#define LDSM_X4(r0, r1, r2, r3, addr) \
    asm volatile("ldmatrix.sync.aligned.m8n8.x4.shared.b16 {%0,%1,%2,%3}, [%4];" \
        : "=r"(r0), "=r"(r1), "=r"(r2), "=r"(r3) : "r"(addr))

#define LDSM_X2(r0, r1, addr) \
    asm volatile("ldmatrix.sync.aligned.m8n8.x2.shared.b16 {%0,%1}, [%2];" \
        : "=r"(r0), "=r"(r1) : "r"(addr))

#define MMA16816(d, a0, a1, a2, a3, b0, b1) \
    asm volatile("mma.sync.aligned.m16n8k16.row.col.f32.f16.f16.f32 " \
        "{%0,%1,%2,%3}, {%4,%5,%6,%7}, {%8,%9}, {%0,%1,%2,%3};" \
        : "+f"((d)[0]), "+f"((d)[1]), "+f"((d)[2]), "+f"((d)[3]) \
        : "r"(a0), "r"(a1), "r"(a2), "r"(a3), "r"(b0), "r"(b1))

// =====================================================================
// Phase 1: z = sigmoid(x @ W + bw), HMMA 3-term fp16 split.
// CTA tile 128m x 128n, K chunks of 64.  8 warps = 2m x 4n.
// B staging vectorized (float4 W loads).  Resets phase-2 counters.
// =====================================================================
#define P1_SMEM 65536   // 4 x 16KB: Ahi, Alo, Bhi, Blo

__global__ __launch_bounds__(256) void phase1(const float* __restrict__ x,
                                              const float* __restrict__ W,
                                              const float* __restrict__ bw) {
    if (blockIdx.x == 0 && blockIdx.y == 0 && threadIdx.x < 8)
        g_cnt[threadIdx.x] = 0;

    extern __shared__ __align__(16) unsigned char sm1[];
    unsigned char* sAh = sm1;
    unsigned char* sAl = sm1 + 16384;
    unsigned char* sBh = sm1 + 32768;
    unsigned char* sBl = sm1 + 49152;
    const uint32_t uAh = smem_u32(sAh), uAl = smem_u32(sAl);
    const uint32_t uBh = smem_u32(sBh), uBl = smem_u32(sBl);

    const int tid = threadIdx.x;
    const int w = tid >> 5, lane = tid & 31;
    const int wm = w >> 2, wn = w & 3;
    const int m0 = blockIdx.y * 128;
    const int n0 = blockIdx.x * 128;

    const int q = lane >> 3, lr = lane & 7, cq = q >> 1;
    const int rowA = lr + (q & 1) * 8;
    const int rowB = lane & 7;
    const int cb = (lane >> 3) & 1;

    float acc[4][4][4];
#pragma unroll
    for (int a = 0; a < 4; ++a)
#pragma unroll
        for (int b = 0; b < 4; ++b)
#pragma unroll
            for (int cc = 0; cc < 4; ++cc) acc[a][b][cc] = 0.f;

    for (int kc = 0; kc < 8; ++kc) {
        const int k0 = kc * 64;
        __syncthreads();
        // ---- stage A: x[m0..+128][k0..+64] fp32 -> hi/lo fp16, swizzled ----
#pragma unroll
        for (int i = 0; i < 8; ++i) {
            const int s = tid + i * 256;            // 0..2047 float4 slots
            const int r = s >> 4;                    // 0..127
            const int c4 = (s & 15) << 2;            // 0..60
            const float4 v = *(const float4*)&x[(size_t)(m0 + r) * Idim + k0 + c4];
            const __half h0 = __float2half_rn(v.x), h1 = __float2half_rn(v.y);
            const __half h2 = __float2half_rn(v.z), h3 = __float2half_rn(v.w);
            const int base = r * 128 + ((((c4 >> 3)) ^ (r & 7)) << 4) + ((c4 >> 2) & 1) * 8;
            *(uint2*)(sAh + base) = make_uint2(packh2(h0, h1), packh2(h2, h3));
            *(uint2*)(sAl + base) = make_uint2(
                packh2(__float2half_rn(v.x - __half2float(h0)),
                       __float2half_rn(v.y - __half2float(h1))),
                packh2(__float2half_rn(v.z - __half2float(h2)),
                       __float2half_rn(v.w - __half2float(h3))));
        }
        // ---- stage B: W[k0..+64][n0..+128] -> transposed (n,k), hi/lo ----
        // vectorized: 8 x LDG.128 per thread
#pragma unroll
        for (int i = 0; i < 8; ++i) {
            const int s2 = tid + i * 256;            // 0..2047 float4 slots
            const int kk = s2 >> 5;                   // 0..63
            const int nn4 = (s2 & 31) << 2;           // 0..124
            const float4 v = *(const float4*)&W[(size_t)(k0 + kk) * Hdim + n0 + nn4];
            const float vv[4] = {v.x, v.y, v.z, v.w};
#pragma unroll
            for (int j = 0; j < 4; ++j) {
                const int nn = nn4 + j;
                const __half hv = __float2half_rn(vv[j]);
                const int ad = nn * 128 + ((((kk >> 3)) ^ (nn & 7)) << 4) + (kk & 7) * 2;
                *(__half*)(sBh + ad) = hv;
                *(__half*)(sBl + ad) = __float2half_rn(vv[j] - __half2float(hv));
            }
        }
        __syncthreads();
        // ---- mma over 4 k16 steps ----
#pragma unroll
        for (int kt = 0; kt < 4; ++kt) {
            uint32_t ah[4][4], al[4][4], bhf[4][2], blf[4][2];
#pragma unroll
            for (int mt = 0; mt < 4; ++mt) {
                const int r = wm * 64 + mt * 16 + rowA;
                const uint32_t off = (uint32_t)(r * 128 + (((2 * kt + cq) ^ (r & 7)) << 4));
                LDSM_X4(ah[mt][0], ah[mt][1], ah[mt][2], ah[mt][3], uAh + off);
                LDSM_X4(al[mt][0], al[mt][1], al[mt][2], al[mt][3], uAl + off);
            }
#pragma unroll
            for (int nt = 0; nt < 4; ++nt) {
                const int rn = wn * 32 + nt * 8 + rowB;
                const uint32_t offb = (uint32_t)(rn * 128 + (((2 * kt + cb) ^ (rn & 7)) << 4));
                LDSM_X2(bhf[nt][0], bhf[nt][1], uBh + offb);
                LDSM_X2(blf[nt][0], blf[nt][1], uBl + offb);
            }
#pragma unroll
            for (int mt = 0; mt < 4; ++mt)
#pragma unroll
                for (int nt = 0; nt < 4; ++nt) {
                    MMA16816(acc[mt][nt], ah[mt][0], ah[mt][1], ah[mt][2], ah[mt][3],
                             bhf[nt][0], bhf[nt][1]);
                    MMA16816(acc[mt][nt], al[mt][0], al[mt][1], al[mt][2], al[mt][3],
                             bhf[nt][0], bhf[nt][1]);
                    MMA16816(acc[mt][nt], ah[mt][0], ah[mt][1], ah[mt][2], ah[mt][3],
                             blf[nt][0], blf[nt][1]);
                }
        }
    }

    // ---- epilogue: bias + sigmoid + store ----
    const int gid = lane >> 2, tig = lane & 3;
#pragma unroll
    for (int nt = 0; nt < 4; ++nt) {
        const int gn = n0 + wn * 32 + nt * 8 + tig * 2;
        const float b0 = bw[gn], b1 = bw[gn + 1];
#pragma unroll
        for (int mt = 0; mt < 4; ++mt) {
            const int gm = m0 + wm * 64 + mt * 16 + gid;
            const float z0 = 1.f / (1.f + __expf(-(acc[mt][nt][0] + b0)));
            const float z1 = 1.f / (1.f + __expf(-(acc[mt][nt][1] + b1)));
            const float z2 = 1.f / (1.f + __expf(-(acc[mt][nt][2] + b0)));
            const float z3 = 1.f / (1.f + __expf(-(acc[mt][nt][3] + b1)));
            *(float2*)&g_z[(size_t)gm * Hdim + gn]       = make_float2(z0, z1);
            *(float2*)&g_z[(size_t)(gm + 8) * Hdim + gn] = make_float2(z2, z3);
        }
    }
}

// =====================================================================
// Phase 2: HMMA recurrence.  128 CTAs = 4 groups x 32.
// Per step:
//   mma -> red4 -> syncthreads
//   w0,w1: epilogue -> bar.sync(1,64) -> tid0 release
//   w7 lane0 (concurrently): acquire-spin on group counter
//   syncthreads  (joins epilogue + spinner; CTA-fence gives visibility)
//   all: load y(t+1) -> smem, z prefetch -> syncthreads
// =====================================================================
__global__ __launch_bounds__(256, 1) void phase2(const float* __restrict__ Rm,
                                                 const float* __restrict__ br,
                                                 const float* __restrict__ y0,
                                                 const float* __restrict__ c0,
                                                 float* __restrict__ out,
                                                 int tail) {
    __shared__ __align__(16) unsigned char sAhi[16 * 1024];   // 16 rows x 512 fp16
    __shared__ __align__(16) unsigned char sAlo[16 * 1024];
    __shared__ float4 red4[8 * 32];

    const int tid  = threadIdx.x;
    const int w    = tid >> 5;
    const int lane = tid & 31;
    const int g    = blockIdx.x >> 5;     // 0..3
    const int c    = blockIdx.x & 31;     // 0..31
    const int cbase = c * 16;
    const int nw = w & 3;                 // n-tile
    const int kh = w >> 2;                // K half
    const int tig = lane & 3;
    const int gid = lane >> 2;
    unsigned* cnt = &g_cnt[g];

    // ---- resident B fragments: R slice hi/lo fp16 ----
    uint32_t bh[16][2], bl[16][2];
    {
        const int nCol = (nw < 2) ? (cbase + nw * 8 + gid)
                                  : (512 + cbase + (nw - 2) * 8 + gid);
#pragma unroll
        for (int kt = 0; kt < 16; ++kt) {
            const int k0 = (kh * 16 + kt) * 16 + tig * 2;
            float v0 = Rm[(size_t)(k0)     * N2H + nCol];
            float v1 = Rm[(size_t)(k0 + 1) * N2H + nCol];
            float v2 = Rm[(size_t)(k0 + 8) * N2H + nCol];
            float v3 = Rm[(size_t)(k0 + 9) * N2H + nCol];
            __half h0 = __float2half_rn(v0), h1 = __float2half_rn(v1);
            __half h2 = __float2half_rn(v2), h3 = __float2half_rn(v3);
            bh[kt][0] = packh2(h0, h1);
            bh[kt][1] = packh2(h2, h3);
            bl[kt][0] = packh2(__float2half_rn(v0 - __half2float(h0)),
                               __float2half_rn(v1 - __half2float(h1)));
            bl[kt][1] = packh2(__float2half_rn(v2 - __half2float(h2)),
                               __float2half_rn(v3 - __half2float(h3)));
        }
    }

    // ---- ldmatrix lane addressing ----
    const int q  = lane >> 3;
    const int lr = lane & 7;
    const int rowA = lr + (q & 1) * 8;
    const int cq   = q >> 1;
    const uint32_t aHiBase = smem_u32(sAhi) + (uint32_t)rowA * 1024u;
    const uint32_t aLoBase = smem_u32(sAlo) + (uint32_t)rowA * 1024u;

    // ---- epilogue state (warps 0,1) ----
    const int h0  = cbase + nw * 8 + tig * 2;
    const int gbA = g * 16 + gid;
    const int gbB = gbA + 8;
    float bi0 = 0, bi1 = 0, bo0 = 0, bo1 = 0;
    float cA0 = 0, cA1 = 0, cB0 = 0, cB1 = 0;
    if (w < 2) {
        bi0 = br[h0];       bi1 = br[h0 + 1];
        bo0 = br[512 + h0]; bo1 = br[512 + h0 + 1];
        cA0 = c0[(size_t)gbA * Hdim + h0];
        cA1 = c0[(size_t)gbA * Hdim + h0 + 1];
        cB0 = c0[(size_t)gbB * Hdim + h0];
        cB1 = c0[(size_t)gbB * Hdim + h0 + 1];
    }

    // ---- init y buffer 0 (CTA 0 of each group) ----
    if (c == 0) {
        for (int i = tid; i < 16 * 512; i += 256) {
            const int row = i >> 9, col = i & 511;
            const float v = y0[(size_t)(g * 16 + row) * Hdim + col];
            const __half hi = __float2half_rn(v);
            g_yhi[(size_t)(g * 16 + row) * 512 + col] = *(const unsigned short*)&hi;
            const __half lo = __float2half_rn(v - __half2float(hi));
            g_ylo[(size_t)(g * 16 + row) * 512 + col] = *(const unsigned short*)&lo;
        }
    }
    group_barrier(cnt, 32u);    // cnt = 32 after all prologues

    // ---- load y(0) into smem ----
    {
        const uint4* srcH = (const uint4*)(g_yhi + (size_t)(g * 16) * 512);
        const uint4* srcL = (const uint4*)(g_ylo + (size_t)(g * 16) * 512);
#pragma unroll
        for (int i = 0; i < 4; ++i) {
            const int u = tid + i * 256;
            const int row = u >> 6, ch = u & 63;
            const uint4 vh = __ldcg(srcH + u);
            const uint4 vl = __ldcg(srcL + u);
            const int soff = row * 1024 + ((ch ^ (row & 7)) << 4);
            *(uint4*)(sAhi + soff) = vh;
            *(uint4*)(sAlo + soff) = vl;
        }
    }
    __syncthreads();

    // ---- prefetch z(0) ----
    float2 zA = make_float2(0, 0), zB = make_float2(0, 0);
    if (w < 2) {
        zA = __ldcs((const float2*)&g_z[((size_t)gbA * Tdim + 0) * Hdim + h0]);
        zB = __ldcs((const float2*)&g_z[((size_t)gbB * Tdim + 0) * Hdim + h0]);
    }

    for (int t = 0; t < Tdim; ++t) {
        // ---- 3-term split mma over this warp's K half ----
        {
            float dhh[4] = {0, 0, 0, 0}, dlh[4] = {0, 0, 0, 0}, dhl[4] = {0, 0, 0, 0};
#pragma unroll
            for (int kt = 0; kt < 16; ++kt) {
                const int ktg = kh * 16 + kt;
                const uint32_t xoff = (uint32_t)(((ktg * 2 + cq) ^ lr) << 4);
                uint32_t ah0, ah1, ah2, ah3, al0, al1, al2, al3;
                LDSM_X4(ah0, ah1, ah2, ah3, aHiBase + xoff);
                LDSM_X4(al0, al1, al2, al3, aLoBase + xoff);
                MMA16816(dhh, ah0, ah1, ah2, ah3, bh[kt][0], bh[kt][1]);
                MMA16816(dlh, al0, al1, al2, al3, bh[kt][0], bh[kt][1]);
                MMA16816(dhl, ah0, ah1, ah2, ah3, bl[kt][0], bl[kt][1]);
            }
            red4[w * 32 + lane] = make_float4(dhh[0] + dlh[0] + dhl[0],
                                              dhh[1] + dlh[1] + dhl[1],
                                              dhh[2] + dlh[2] + dhl[2],
                                              dhh[3] + dlh[3] + dhl[3]);
        }
        __syncthreads();    // red4 ready; ldsm reads of y smem complete

        // ---- epilogue (w0,w1) concurrent with acquire-spin (w7 lane0) ----
        if (w < 2) {
            const float4 iA = red4[w * 32 + lane];
            const float4 iB = red4[(w + 4) * 32 + lane];
            const float4 oA = red4[(w + 2) * 32 + lane];
            const float4 oB = red4[(w + 6) * 32 + lane];

            const float ivA0 = tanh_fast(iA.x + iB.x + bi0);
            const float ivA1 = tanh_fast(iA.y + iB.y + bi1);
            const float ivB0 = tanh_fast(iA.z + iB.z + bi0);
            const float ivB1 = tanh_fast(iA.w + iB.w + bi1);
            const float ovA0 = tanh_fast(oA.x + oB.x + bo0);
            const float ovA1 = tanh_fast(oA.y + oB.y + bo1);
            const float ovB0 = tanh_fast(oA.z + oB.z + bo0);
            const float ovB1 = tanh_fast(oA.w + oB.w + bo1);

            cA0 += ivA0 * zA.x;  cA1 += ivA1 * zA.y;
            cB0 += ivB0 * zB.x;  cB1 += ivB1 * zB.y;

            const float yA0 = ovA0 * tanh_fast(cA0);
            const float yA1 = ovA1 * tanh_fast(cA1);
            const float yB0 = ovB0 * tanh_fast(cB0);
            const float yB1 = ovB1 * tanh_fast(cB1);

            *(float2*)&out[((size_t)t * Bdim + gbA) * Hdim + h0] = make_float2(yA0, yA1);
            *(float2*)&out[((size_t)t * Bdim + gbB) * Hdim + h0] = make_float2(yB0, yB1);

            const int nbuf = (t + 1) & 1;
            const __half hA0 = __float2half_rn(yA0), hA1 = __float2half_rn(yA1);
            const __half hB0 = __float2half_rn(yB0), hB1 = __float2half_rn(yB1);
            *(uint32_t*)&g_yhi[((size_t)nbuf * Bdim + gbA) * Hdim + h0] = packh2(hA0, hA1);
            *(uint32_t*)&g_yhi[((size_t)nbuf * Bdim + gbB) * Hdim + h0] = packh2(hB0, hB1);
            *(uint32_t*)&g_ylo[((size_t)nbuf * Bdim + gbA) * Hdim + h0] =
                packh2(__float2half_rn(yA0 - __half2float(hA0)),
                       __float2half_rn(yA1 - __half2float(hA1)));
            *(uint32_t*)&g_ylo[((size_t)nbuf * Bdim + gbB) * Hdim + h0] =
                packh2(__float2half_rn(yB0 - __half2float(hB0)),
                       __float2half_rn(yB1 - __half2float(hB1)));

            if (tail && t == Tdim - 1) {
                const size_t base = (size_t)Tdim * Bdim * Hdim;
                out[base + (size_t)gbA * Hdim + h0]     = yA0;
                out[base + (size_t)gbA * Hdim + h0 + 1] = yA1;
                out[base + (size_t)gbB * Hdim + h0]     = yB0;
                out[base + (size_t)gbB * Hdim + h0 + 1] = yB1;
                const size_t cb = base + (size_t)Bdim * Hdim;
                out[cb + (size_t)gbA * Hdim + h0]     = cA0;
                out[cb + (size_t)gbA * Hdim + h0 + 1] = cA1;
                out[cb + (size_t)gbB * Hdim + h0]     = cB0;
                out[cb + (size_t)gbB * Hdim + h0 + 1] = cB1;
            }

            // y stores of BOTH epilogue warps ordered before the release
            asm volatile("bar.sync 1, 64;" ::: "memory");
            if (tid == 0) red_rel_add(cnt, 1u);
        } else if (w == 7 && lane == 0 && t < Tdim - 1) {
            spin_until(cnt, 32u * (unsigned)(t + 2));   // single poller, hidden
        }
        __syncthreads();    // join epilogue + spinner; CTA fence -> visibility

        // ---- load y(t+1) into smem ----
        if (t < Tdim - 1) {
            const int buf = (t + 1) & 1;
            const uint4* srcH = (const uint4*)(g_yhi + ((size_t)buf * Bdim + g * 16) * 512);
            const uint4* srcL = (const uint4*)(g_ylo + ((size_t)buf * Bdim + g * 16) * 512);
#pragma unroll
            for (int i = 0; i < 4; ++i) {
                const int u = tid + i * 256;
                const int row = u >> 6, ch = u & 63;
                const uint4 vh = __ldcg(srcH + u);
                const uint4 vl = __ldcg(srcL + u);
                const int soff = row * 1024 + ((ch ^ (row & 7)) << 4);
                *(uint4*)(sAhi + soff) = vh;
                *(uint4*)(sAlo + soff) = vl;
            }
            if (w < 2) {    // prefetch z(t+1); consumed after next mma+sync
                zA = __ldcs((const float2*)&g_z[((size_t)gbA * Tdim + t + 1) * Hdim + h0]);
                zB = __ldcs((const float2*)&g_z[((size_t)gbB * Tdim + t + 1) * Hdim + h0]);
            }
            __syncthreads();    // y smem complete before next mma
        }
    }
}

// =====================================================================
extern "C" void kernel_launch(void* const* d_in, const int* in_sizes, int n_in,
                              void* d_out, int out_size) {
    const float* x  = (const float*)d_in[0];
    const float* W  = (const float*)d_in[1];
    const float* R  = (const float*)d_in[2];
    const float* br = (const float*)d_in[3];
    const float* bw = (const float*)d_in[4];
    const float* y0 = (const float*)d_in[5];
    const float* c0 = (const float*)d_in[6];
    float* out = (float*)d_out;

    cudaFuncSetAttribute(phase1, cudaFuncAttributeMaxDynamicSharedMemorySize, P1_SMEM);

    dim3 g1(Hdim / 128, (Bdim * Tdim) / 128);   // (4, 512)
    phase1<<<g1, 256, P1_SMEM>>>(x, W, bw);

    const long long full = (long long)Tdim * Bdim * Hdim + 2LL * Bdim * Hdim;
    const int tail = ((long long)out_size >= full) ? 1 : 0;
    phase2<<<128, 256>>>(R, br, y0, c0, out, tail);
}